// round 12
// baseline (speedup 1.0000x reference)
#include <cuda_runtime.h>
#include <math.h>
#include <stdint.h>

// Problem dims (fixed by reference)
constexpr int BB = 4;
constexpr int SS = 2048;
constexpr int DD = 1024;
constexpr int HH = 1024;

// Scratch (device globals -- no allocation allowed)
__device__ float g_Q[BB * SS * HH];
__device__ float g_K[BB * SS * HH];
__device__ float g_V[BB * SS * HH];
__device__ float g_P[BB * SS * SS];     // scores / probs (in-place softmax)
__device__ float g_X[BB * SS * DD];     // tf32-rounded x
__device__ float g_W[3 * DD * HH];      // tf32-rounded Wq|Wk|Wv

__device__ __forceinline__ void cpa16(uint32_t smem_dst, const void* gsrc) {
    asm volatile("cp.async.cg.shared.global [%0], [%1], 16;\n"
                 :: "r"(smem_dst), "l"(gsrc));
}
__device__ __forceinline__ float tf32r(float f) {
    uint32_t r;
    asm("cvt.rna.tf32.f32 %0, %1;\n" : "=r"(r) : "f"(f));
    return __uint_as_float(r);
}

// ---------------------------------------------------------------------------
// Elementwise tf32 rounding (producer-side; removes cvt from GEMM hot loops)
// ---------------------------------------------------------------------------
__global__ __launch_bounds__(256) void round_tf32_kernel(
    const float* __restrict__ in, float* __restrict__ out, int n4)
{
    int i = blockIdx.x * blockDim.x + threadIdx.x;
    if (i < n4) {
        float4 v = ((const float4*)in)[i];
        v.x = tf32r(v.x); v.y = tf32r(v.y);
        v.z = tf32r(v.z); v.w = tf32r(v.w);
        ((float4*)out)[i] = v;
    }
}

// ---------------------------------------------------------------------------
// tf32 tensor-core GEMM: 128x128x16 tile, 256 threads (8 warps, 2x4),
// warp tile 64x32, mma.sync.m16n8k8.tf32, 4-stage cp.async pipeline.
// Operands must be pre-rounded to tf32 by their producers.
// TRANSB=false: C = A[M,K] * B[K,N] * scale + bias
// TRANSB=true : C = A[M,K] * B[N,K]^T * scale + bias
// ROUND_OUT: round the result to tf32 before storing (for Q/K/V).
// ---------------------------------------------------------------------------
template <bool TRANSB, bool ROUND_OUT>
__global__ __launch_bounds__(256, 2) void mm_tf32_kernel(
    const float* __restrict__ A, const float* __restrict__ Bm,
    const float* __restrict__ bias, float* __restrict__ C,
    int M, int N, int K, float scale,
    size_t strideA, size_t strideB, size_t strideC)
{
    constexpr int STAGES = 4;
    constexpr int BK  = 16;
    constexpr int AST = 20;                      // A smem row stride (floats)
    constexpr int BROWS = TRANSB ? 128 : BK;
    constexpr int BST   = TRANSB ? 20  : 136;    // B smem row stride (floats)
    constexpr int ASTG_F = 128 * AST;            // floats per A stage
    constexpr int BSTG_F = BROWS * BST;          // floats per B stage

    extern __shared__ float smem[];
    float* As = smem;                            // [STAGES][ASTG_F]
    float* Bs = smem + STAGES * ASTG_F;          // [STAGES][BSTG_F]

    A  += (size_t)blockIdx.z * strideA;
    Bm += (size_t)blockIdx.z * strideB;
    C  += (size_t)blockIdx.z * strideC;

    const int tid  = threadIdx.x;
    const int lane = tid & 31;
    const int warp = tid >> 5;
    const int wm = warp >> 2;          // 0..1  (64-row slab)
    const int wn = warp & 3;           // 0..3  (32-col slab)
    const int gID = lane >> 2;         // 0..7
    const int tq  = lane & 3;          // 0..3

    const int bm = blockIdx.y * 128;
    const int bn = blockIdx.x * 128;

    // ---- global load mappings ----
    const int a_row = tid >> 1;
    const int a_col = (tid & 1) * 8;
    const float* gA = A + (size_t)(bm + a_row) * K + a_col;

    const int bnn_row = tid >> 5;
    const int bnn_col = (tid & 31) * 4;
    const float* gB = TRANSB
        ? (Bm + (size_t)(bn + a_row) * K + a_col)
        : (Bm + (size_t)bnn_row * N + bn + bnn_col);

    const uint32_t sA0 = (uint32_t)__cvta_generic_to_shared(
        &As[a_row * AST + a_col]);
    const uint32_t sB0 = TRANSB
        ? (uint32_t)__cvta_generic_to_shared(&Bs[a_row * BST + a_col])
        : (uint32_t)__cvta_generic_to_shared(&Bs[bnn_row * BST + bnn_col]);

    float acc[4][4][4];
    #pragma unroll
    for (int mi = 0; mi < 4; mi++)
        #pragma unroll
        for (int ni = 0; ni < 4; ni++)
            #pragma unroll
            for (int q = 0; q < 4; q++) acc[mi][ni][q] = 0.0f;

    const int ntiles = K / BK;

    auto load_tile = [&](int t, int s) {
        uint32_t sa = sA0 + s * (ASTG_F * 4);
        uint32_t sb = sB0 + s * (BSTG_F * 4);
        const float* ga = gA + t * BK;
        cpa16(sa,      ga);
        cpa16(sa + 16, ga + 4);
        if (TRANSB) {
            const float* gb = gB + t * BK;
            cpa16(sb,      gb);
            cpa16(sb + 16, gb + 4);
        } else {
            const float* gb = gB + (size_t)t * BK * N;
            cpa16(sb,               gb);
            cpa16(sb + 8 * BST * 4, gb + (size_t)8 * N);
        }
    };

    // Prologue: prefetch STAGES-1 tiles, one commit group each
    #pragma unroll
    for (int s = 0; s < STAGES - 1; s++) {
        load_tile(s, s);
        asm volatile("cp.async.commit_group;\n" ::);
    }

    for (int t = 0; t < ntiles; t++) {
        // Tile t is complete once only the newest STAGES-2 groups may be
        // pending (empty tail groups keep the count exact).
        asm volatile("cp.async.wait_group %0;\n" :: "n"(STAGES - 2));
        __syncthreads();

        const int nt = t + STAGES - 1;
        if (nt < ntiles) load_tile(nt, nt & (STAGES - 1));
        asm volatile("cp.async.commit_group;\n" ::);   // possibly empty group

        const float* as = As + (t & (STAGES - 1)) * ASTG_F;
        const float* bs = Bs + (t & (STAGES - 1)) * BSTG_F;

        #pragma unroll
        for (int ks = 0; ks < 2; ks++) {
            const int k0 = ks * 8;
            uint32_t af[4][4], bf[4][2];
            #pragma unroll
            for (int mi = 0; mi < 4; mi++) {
                const int r = wm * 64 + mi * 16 + gID;
                af[mi][0] = __float_as_uint(as[(r    ) * AST + k0 + tq    ]);
                af[mi][1] = __float_as_uint(as[(r + 8) * AST + k0 + tq    ]);
                af[mi][2] = __float_as_uint(as[(r    ) * AST + k0 + tq + 4]);
                af[mi][3] = __float_as_uint(as[(r + 8) * AST + k0 + tq + 4]);
            }
            #pragma unroll
            for (int ni = 0; ni < 4; ni++) {
                const int n = wn * 32 + ni * 8 + gID;
                if (TRANSB) {
                    bf[ni][0] = __float_as_uint(bs[n * BST + k0 + tq    ]);
                    bf[ni][1] = __float_as_uint(bs[n * BST + k0 + tq + 4]);
                } else {
                    bf[ni][0] = __float_as_uint(bs[(k0 + tq    ) * BST + n]);
                    bf[ni][1] = __float_as_uint(bs[(k0 + tq + 4) * BST + n]);
                }
            }
            #pragma unroll
            for (int mi = 0; mi < 4; mi++)
                #pragma unroll
                for (int ni = 0; ni < 4; ni++) {
                    asm volatile(
                        "mma.sync.aligned.m16n8k8.row.col.f32.tf32.tf32.f32 "
                        "{%0,%1,%2,%3}, {%4,%5,%6,%7}, {%8,%9}, {%0,%1,%2,%3};\n"
                        : "+f"(acc[mi][ni][0]), "+f"(acc[mi][ni][1]),
                          "+f"(acc[mi][ni][2]), "+f"(acc[mi][ni][3])
                        : "r"(af[mi][0]), "r"(af[mi][1]),
                          "r"(af[mi][2]), "r"(af[mi][3]),
                          "r"(bf[ni][0]), "r"(bf[ni][1]));
                }
        }
    }

    // ---- epilogue: scale, optional bias, optional tf32 rounding, store ----
    #pragma unroll
    for (int mi = 0; mi < 4; mi++) {
        const int r0 = bm + wm * 64 + mi * 16 + gID;
        #pragma unroll
        for (int ni = 0; ni < 4; ni++) {
            const int c = bn + wn * 32 + ni * 8 + tq * 2;
            float b0 = 0.0f, b1 = 0.0f;
            if (bias) { b0 = bias[c]; b1 = bias[c + 1]; }
            float2 v0, v1;
            v0.x = acc[mi][ni][0] * scale + b0;
            v0.y = acc[mi][ni][1] * scale + b1;
            v1.x = acc[mi][ni][2] * scale + b0;
            v1.y = acc[mi][ni][3] * scale + b1;
            if (ROUND_OUT) {
                v0.x = tf32r(v0.x); v0.y = tf32r(v0.y);
                v1.x = tf32r(v1.x); v1.y = tf32r(v1.y);
            }
            *(float2*)&C[(size_t)r0 * N + c]       = v0;
            *(float2*)&C[(size_t)(r0 + 8) * N + c] = v1;
        }
    }
}

// ---------------------------------------------------------------------------
// Row softmax, in place, tf32-rounded output (it feeds the PV GEMM).
// One block per row (row length SS=2048), 256 threads.
// ---------------------------------------------------------------------------
__global__ __launch_bounds__(256) void softmax_kernel(float* __restrict__ P)
{
    float4* p = (float4*)(P + (size_t)blockIdx.x * SS);
    const int t = threadIdx.x;
    __shared__ float red[256];

    float4 v[2];
    float m = -1e30f;
    #pragma unroll
    for (int i = 0; i < 2; i++) {
        v[i] = p[t + i * 256];
        m = fmaxf(fmaxf(fmaxf(v[i].x, v[i].y), fmaxf(v[i].z, v[i].w)), m);
    }
    red[t] = m;
    __syncthreads();
    #pragma unroll
    for (int s = 128; s > 0; s >>= 1) {
        if (t < s) red[t] = fmaxf(red[t], red[t + s]);
        __syncthreads();
    }
    m = red[0];
    __syncthreads();

    float sum = 0.0f;
    #pragma unroll
    for (int i = 0; i < 2; i++) {
        v[i].x = __expf(v[i].x - m); sum += v[i].x;
        v[i].y = __expf(v[i].y - m); sum += v[i].y;
        v[i].z = __expf(v[i].z - m); sum += v[i].z;
        v[i].w = __expf(v[i].w - m); sum += v[i].w;
    }
    red[t] = sum;
    __syncthreads();
    #pragma unroll
    for (int s = 128; s > 0; s >>= 1) {
        if (t < s) red[t] += red[t + s];
        __syncthreads();
    }
    const float inv = 1.0f / red[0];

    #pragma unroll
    for (int i = 0; i < 2; i++) {
        float4 o;
        o.x = tf32r(v[i].x * inv);
        o.y = tf32r(v[i].y * inv);
        o.z = tf32r(v[i].z * inv);
        o.w = tf32r(v[i].w * inv);
        p[t + i * 256] = o;
    }
}

// ---------------------------------------------------------------------------
extern "C" void kernel_launch(void* const* d_in, const int* in_sizes, int n_in,
                              void* d_out, int out_size)
{
    const float* x  = (const float*)d_in[0];
    const float* Wq = (const float*)d_in[1];
    const float* bq = (const float*)d_in[2];
    const float* Wk = (const float*)d_in[3];
    const float* bk = (const float*)d_in[4];
    const float* Wv = (const float*)d_in[5];
    const float* bv = (const float*)d_in[6];
    float* out = (float*)d_out;

    float *Q, *K, *V, *P, *X, *W;
    cudaGetSymbolAddress((void**)&Q, g_Q);
    cudaGetSymbolAddress((void**)&K, g_K);
    cudaGetSymbolAddress((void**)&V, g_V);
    cudaGetSymbolAddress((void**)&P, g_P);
    cudaGetSymbolAddress((void**)&X, g_X);
    cudaGetSymbolAddress((void**)&W, g_W);

    // Dynamic smem sizes (4 stages)
    constexpr int SMEM_NN = 4 * (128 * 20 + 16 * 136) * 4;   // 75776 B
    constexpr int SMEM_NT = 4 * (128 * 20 + 128 * 20) * 4;   // 81920 B
    cudaFuncSetAttribute(mm_tf32_kernel<false, true>,
        cudaFuncAttributeMaxDynamicSharedMemorySize, SMEM_NN);
    cudaFuncSetAttribute(mm_tf32_kernel<false, false>,
        cudaFuncAttributeMaxDynamicSharedMemorySize, SMEM_NN);
    cudaFuncSetAttribute(mm_tf32_kernel<true, false>,
        cudaFuncAttributeMaxDynamicSharedMemorySize, SMEM_NT);

    dim3 blk(256);
    const int M = BB * SS;  // 8192

    // Pre-round x and weights to tf32 (producers of GEMM operands)
    round_tf32_kernel<<<(M * DD / 4 + 255) / 256, 256>>>(x, X, M * DD / 4);
    round_tf32_kernel<<<(DD * HH / 4 + 255) / 256, 256>>>(Wq, W,               DD * HH / 4);
    round_tf32_kernel<<<(DD * HH / 4 + 255) / 256, 256>>>(Wk, W + DD * HH,     DD * HH / 4);
    round_tf32_kernel<<<(DD * HH / 4 + 255) / 256, 256>>>(Wv, W + 2 * DD * HH, DD * HH / 4);

    // QKV projections: [8192,1024] x [1024,1024] + bias, tf32-rounded outputs
    mm_tf32_kernel<false, true><<<dim3(HH / 128, M / 128, 1), blk, SMEM_NN>>>(
        X, W,               bq, Q, M, HH, DD, 1.0f, 0, 0, 0);
    mm_tf32_kernel<false, true><<<dim3(HH / 128, M / 128, 1), blk, SMEM_NN>>>(
        X, W + DD * HH,     bk, K, M, HH, DD, 1.0f, 0, 0, 0);
    mm_tf32_kernel<false, true><<<dim3(HH / 128, M / 128, 1), blk, SMEM_NN>>>(
        X, W + 2 * DD * HH, bv, V, M, HH, DD, 1.0f, 0, 0, 0);

    // Scores: P[b] = Q[b] * K[b]^T * (1/sqrt(H)), batched over z
    mm_tf32_kernel<true, false><<<dim3(SS / 128, SS / 128, BB), blk, SMEM_NT>>>(
        Q, K, nullptr, P, SS, SS, HH, 0.03125f,
        (size_t)SS * HH, (size_t)SS * HH, (size_t)SS * SS);

    // Softmax over rows of P (tf32-rounded output)
    softmax_kernel<<<BB * SS, 256>>>(P);

    // Output: out[b] = P[b] * V[b]  (fp32 store, no rounding)
    mm_tf32_kernel<false, false><<<dim3(HH / 128, SS / 128, BB), blk, SMEM_NN>>>(
        P, V, nullptr, out, SS, HH, SS, 1.0f,
        (size_t)SS * SS, (size_t)SS * HH, (size_t)SS * HH);
}